// round 2
// baseline (speedup 1.0000x reference)
#include <cuda_runtime.h>
#include <cuda_bf16.h>
#include <cstdint>

// Problem constants
#define TT 512
#define BB 64
#define II 256
#define HH 1024
#define OO 256

#define OUT_ELEMS   (TT * BB * OO)        // 8388608  (outputs section)
#define HID_ELEMS   (TT * BB * HH)        // 33554432 (hidden section)
#define PRE_ELEMS   (TT * BB * HH)

#define REC_CTAS    128
#define REC_THREADS 256
#define REC_SMEM_FLOATS (32 * 1028)       // wR slice [32 cols][1024 k] padded
#define REC_SMEM_BYTES  (REC_SMEM_FLOATS * 4)  // 131584

// Scratch (device globals: no cudaMalloc allowed)
__device__ float    g_pre[PRE_ELEMS];     // x @ wI^T + bR, [T*B][H]
__device__ float    g_h0b[BB * HH];       // h0 broadcast to [B][H]
__device__ unsigned g_arrived = 0;        // monotonic barrier ticket

// ---------------------------------------------------------------------------
// Grid-wide barrier: monotonic ticket counter, wrap-safe, no reset needed
// (state is consistent across graph replays since ticket only grows and the
// round-up arithmetic is modulo-consistent).
// ---------------------------------------------------------------------------
__device__ __forceinline__ void grid_sync() {
    __syncthreads();
    if (threadIdx.x == 0) {
        __threadfence();
        unsigned ticket = atomicAdd(&g_arrived, 1u) + 1u;
        unsigned target = ((ticket + (REC_CTAS - 1u)) / REC_CTAS) * REC_CTAS;
        unsigned cur;
        do {
            asm volatile("ld.acquire.gpu.global.u32 %0, [%1];"
                         : "=r"(cur) : "l"(&g_arrived) : "memory");
        } while ((int)(cur - target) < 0);
        __threadfence();
    }
    __syncthreads();
}

// ---------------------------------------------------------------------------
// Generic fp32 GEMM:  C[M,N] = A[M,K] @ B[N,K]^T + bias[N]
// 64x64 tile, BK=32, 256 threads, 4x4 per-thread tile, smem stored k-major
// with pad 68 so both A and B fragments are LDS.128.
// ---------------------------------------------------------------------------
__global__ void __launch_bounds__(256) gemm_tn_kernel(
    const float* __restrict__ A, const float* __restrict__ B,
    const float* __restrict__ bias, float* __restrict__ C,
    int M, int N, int K)
{
    __shared__ float Ast[32][68];
    __shared__ float Bst[32][68];

    const int tid   = threadIdx.x;
    const int mBase = blockIdx.x * 64;
    const int nBase = blockIdx.y * 64;
    const int lrow  = tid >> 3;          // 0..31
    const int lk    = (tid & 7) << 2;    // 0,4,..,28
    const int tx    = tid & 15;
    const int ty    = tid >> 4;

    float acc[4][4] = {};

    const float* Ap = A + (size_t)(mBase + lrow) * K + lk;
    const float* Bp = B + (size_t)(nBase + lrow) * K + lk;

    for (int k0 = 0; k0 < K; k0 += 32) {
        float4 av0 = *(const float4*)(Ap + k0);
        float4 av1 = *(const float4*)(Ap + (size_t)32 * K + k0);
        float4 bv0 = *(const float4*)(Bp + k0);
        float4 bv1 = *(const float4*)(Bp + (size_t)32 * K + k0);
        __syncthreads();   // previous iteration's compute done before overwrite
        Ast[lk + 0][lrow] = av0.x; Ast[lk + 1][lrow] = av0.y;
        Ast[lk + 2][lrow] = av0.z; Ast[lk + 3][lrow] = av0.w;
        Ast[lk + 0][lrow + 32] = av1.x; Ast[lk + 1][lrow + 32] = av1.y;
        Ast[lk + 2][lrow + 32] = av1.z; Ast[lk + 3][lrow + 32] = av1.w;
        Bst[lk + 0][lrow] = bv0.x; Bst[lk + 1][lrow] = bv0.y;
        Bst[lk + 2][lrow] = bv0.z; Bst[lk + 3][lrow] = bv0.w;
        Bst[lk + 0][lrow + 32] = bv1.x; Bst[lk + 1][lrow + 32] = bv1.y;
        Bst[lk + 2][lrow + 32] = bv1.z; Bst[lk + 3][lrow + 32] = bv1.w;
        __syncthreads();
        #pragma unroll
        for (int k = 0; k < 32; k++) {
            float4 a = *(const float4*)&Ast[k][ty * 4];
            float4 b = *(const float4*)&Bst[k][tx * 4];
            acc[0][0] = fmaf(a.x, b.x, acc[0][0]);
            acc[0][1] = fmaf(a.x, b.y, acc[0][1]);
            acc[0][2] = fmaf(a.x, b.z, acc[0][2]);
            acc[0][3] = fmaf(a.x, b.w, acc[0][3]);
            acc[1][0] = fmaf(a.y, b.x, acc[1][0]);
            acc[1][1] = fmaf(a.y, b.y, acc[1][1]);
            acc[1][2] = fmaf(a.y, b.z, acc[1][2]);
            acc[1][3] = fmaf(a.y, b.w, acc[1][3]);
            acc[2][0] = fmaf(a.z, b.x, acc[2][0]);
            acc[2][1] = fmaf(a.z, b.y, acc[2][1]);
            acc[2][2] = fmaf(a.z, b.z, acc[2][2]);
            acc[2][3] = fmaf(a.z, b.w, acc[2][3]);
            acc[3][0] = fmaf(a.w, b.x, acc[3][0]);
            acc[3][1] = fmaf(a.w, b.y, acc[3][1]);
            acc[3][2] = fmaf(a.w, b.z, acc[3][2]);
            acc[3][3] = fmaf(a.w, b.w, acc[3][3]);
        }
    }

    const float b0 = bias[nBase + tx * 4 + 0];
    const float b1 = bias[nBase + tx * 4 + 1];
    const float b2 = bias[nBase + tx * 4 + 2];
    const float b3 = bias[nBase + tx * 4 + 3];
    #pragma unroll
    for (int i = 0; i < 4; i++) {
        float4 o;
        o.x = acc[i][0] + b0; o.y = acc[i][1] + b1;
        o.z = acc[i][2] + b2; o.w = acc[i][3] + b3;
        *(float4*)&C[(size_t)(mBase + ty * 4 + i) * N + nBase + tx * 4] = o;
    }
}

// ---------------------------------------------------------------------------
// Persistent recurrent kernel: 512 steps of h = tanh(pre_t + h @ wR).
// Grid = 128 CTAs (4 b-tiles of 16 x 32 j-tiles of 32), 256 threads.
// Each CTA keeps its [1024 k][32 j] wR slice in smem (transposed, row-per-j,
// pad 1028) for the whole kernel. h for step t-1 is read straight from the
// hidden-states output section; grid_sync() separates steps.
// Thread (bl=tid>>4, jg=tid&15) computes columns jbase+jg and jbase+jg+16
// for row bBase+bl. Inner loop per 4 k: 1 LDG.128 + 2 LDS.128 + 8 FFMA.
// ---------------------------------------------------------------------------
__global__ void __launch_bounds__(REC_THREADS, 1) rnn_rec_kernel(
    const float* __restrict__ pre,
    const float* __restrict__ h0,
    const float* __restrict__ wR,
    float* __restrict__ hid)
{
    extern __shared__ float wRs[];   // [32][1028]

    const int tid   = threadIdx.x;
    const int bx    = blockIdx.x;
    const int jbase = (bx & 31) * 32;
    const int bBase = (bx >> 5) * 16;

    // Stage this CTA's wR slice: wRs[jj][k] = wR[k*H + jbase + jj]
    for (int idx = tid; idx < 32 * HH; idx += REC_THREADS) {
        int jj = idx & 31;
        int k  = idx >> 5;
        wRs[jj * 1028 + k] = wR[k * HH + jbase + jj];
    }
    // Broadcast h0 -> g_h0b[b][k]
    for (int idx = bx * REC_THREADS + tid; idx < BB * HH; idx += REC_CTAS * REC_THREADS) {
        g_h0b[idx] = h0[idx & (HH - 1)];
    }
    grid_sync();

    const int bl = tid >> 4;
    const int jg = tid & 15;
    const int b  = bBase + bl;
    const int j0 = jbase + jg;
    const int j1 = jbase + jg + 16;
    const float* w0p = wRs + jg * 1028;
    const float* w1p = wRs + (jg + 16) * 1028;

    const float* hOld = g_h0b;
    for (int t = 0; t < TT; t++) {
        const float* hb = hOld + b * HH;
        float a00 = 0.f, a01 = 0.f, a02 = 0.f, a03 = 0.f;
        float a10 = 0.f, a11 = 0.f, a12 = 0.f, a13 = 0.f;
        #pragma unroll 4
        for (int k = 0; k < HH; k += 4) {
            const float4 hv = *reinterpret_cast<const float4*>(hb + k);
            const float4 w0 = *reinterpret_cast<const float4*>(w0p + k);
            const float4 w1 = *reinterpret_cast<const float4*>(w1p + k);
            a00 = fmaf(hv.x, w0.x, a00); a01 = fmaf(hv.y, w0.y, a01);
            a02 = fmaf(hv.z, w0.z, a02); a03 = fmaf(hv.w, w0.w, a03);
            a10 = fmaf(hv.x, w1.x, a10); a11 = fmaf(hv.y, w1.y, a11);
            a12 = fmaf(hv.z, w1.z, a12); a13 = fmaf(hv.w, w1.w, a13);
        }
        const float* preRow = pre + ((size_t)t * BB + b) * HH;
        float h0v = tanhf(preRow[j0] + ((a00 + a01) + (a02 + a03)));
        float h1v = tanhf(preRow[j1] + ((a10 + a11) + (a12 + a13)));
        float* hNew = hid + (size_t)t * (BB * HH);
        hNew[b * HH + j0] = h0v;
        hNew[b * HH + j1] = h1v;
        grid_sync();                 // h_t fully visible before step t+1 reads it
        hOld = hNew;
    }
}

// ---------------------------------------------------------------------------
// Launch: pre-GEMM -> persistent recurrence -> output GEMM (same stream,
// graph-capturable: kernel launches only).
// ---------------------------------------------------------------------------
extern "C" void kernel_launch(void* const* d_in, const int* in_sizes, int n_in,
                              void* d_out, int out_size)
{
    const float* x  = (const float*)d_in[0];
    const float* h0 = (const float*)d_in[1];
    const float* wI = (const float*)d_in[2];
    const float* wR = (const float*)d_in[3];
    const float* wO = (const float*)d_in[4];
    const float* bR = (const float*)d_in[5];
    const float* bO = (const float*)d_in[6];

    float* outp = (float*)d_out;            // [T,B,O]
    float* hid  = outp + OUT_ELEMS;         // [T,B,H]

    float* pre = nullptr;
    cudaGetSymbolAddress((void**)&pre, g_pre);
    cudaFuncSetAttribute(rnn_rec_kernel,
                         cudaFuncAttributeMaxDynamicSharedMemorySize,
                         REC_SMEM_BYTES);

    // pre[T*B, H] = x[T*B, I] @ wI[H, I]^T + bR
    gemm_tn_kernel<<<dim3((TT * BB) / 64, HH / 64, 1), 256>>>(
        x, wI, bR, pre, TT * BB, HH, II);

    // hidden_states (written straight into d_out's hidden section)
    rnn_rec_kernel<<<REC_CTAS, REC_THREADS, REC_SMEM_BYTES>>>(pre, h0, wR, hid);

    // outputs[T*B, O] = hid[T*B, H] @ wO[O, H]^T + bO
    gemm_tn_kernel<<<dim3((TT * BB) / 64, OO / 64, 1), 256>>>(
        hid, wO, bO, outp, TT * BB, OO, HH);
}

// round 3
// speedup vs baseline: 1.7961x; 1.7961x over previous
#include <cuda_runtime.h>
#include <cuda_bf16.h>
#include <cstdint>

// Problem constants
#define TT 512
#define BB 64
#define II 256
#define HH 1024
#define OO 256

#define OUT_ELEMS   (TT * BB * OO)        // outputs section
#define HID_ELEMS   (TT * BB * HH)        // hidden section
#define PRE_ELEMS   (TT * BB * HH)

#define REC_CTAS    128
#define REC_THREADS 256
#define WR_SMEM_FLOATS (32 * 1028)        // wR slice [32 j][1024 k] padded
#define RED_FLOATS  2048                  // 4 ksplit x 512 outputs
#define REC_SMEM_BYTES ((WR_SMEM_FLOATS + RED_FLOATS) * 4)   // 139776

// Scratch (device globals: no cudaMalloc allowed)
__device__ float    g_pre[PRE_ELEMS];     // x @ wI^T + bR, [T*B][H]
__device__ float    g_h0b[BB * HH];       // h0 broadcast to [B][H]
__device__ unsigned g_arrived = 0;        // monotonic barrier ticket

// ---------------------------------------------------------------------------
// Grid-wide barrier: monotonic ticket counter, wrap-safe, no reset needed.
// ---------------------------------------------------------------------------
__device__ __forceinline__ void grid_sync() {
    __syncthreads();
    if (threadIdx.x == 0) {
        __threadfence();
        unsigned ticket = atomicAdd(&g_arrived, 1u) + 1u;
        unsigned target = ((ticket + (REC_CTAS - 1u)) / REC_CTAS) * REC_CTAS;
        unsigned cur;
        do {
            asm volatile("ld.acquire.gpu.global.u32 %0, [%1];"
                         : "=r"(cur) : "l"(&g_arrived) : "memory");
        } while ((int)(cur - target) < 0);
        __threadfence();
    }
    __syncthreads();
}

// ---------------------------------------------------------------------------
// Generic fp32 GEMM:  C[M,N] = A[M,K] @ B[N,K]^T + bias[N]
// (unchanged from last round — measured at the SIMT FFMA roofline)
// ---------------------------------------------------------------------------
__global__ void __launch_bounds__(256) gemm_tn_kernel(
    const float* __restrict__ A, const float* __restrict__ B,
    const float* __restrict__ bias, float* __restrict__ C,
    int M, int N, int K)
{
    __shared__ float Ast[32][68];
    __shared__ float Bst[32][68];

    const int tid   = threadIdx.x;
    const int mBase = blockIdx.x * 64;
    const int nBase = blockIdx.y * 64;
    const int lrow  = tid >> 3;          // 0..31
    const int lk    = (tid & 7) << 2;    // 0,4,..,28
    const int tx    = tid & 15;
    const int ty    = tid >> 4;

    float acc[4][4] = {};

    const float* Ap = A + (size_t)(mBase + lrow) * K + lk;
    const float* Bp = B + (size_t)(nBase + lrow) * K + lk;

    for (int k0 = 0; k0 < K; k0 += 32) {
        float4 av0 = *(const float4*)(Ap + k0);
        float4 av1 = *(const float4*)(Ap + (size_t)32 * K + k0);
        float4 bv0 = *(const float4*)(Bp + k0);
        float4 bv1 = *(const float4*)(Bp + (size_t)32 * K + k0);
        __syncthreads();
        Ast[lk + 0][lrow] = av0.x; Ast[lk + 1][lrow] = av0.y;
        Ast[lk + 2][lrow] = av0.z; Ast[lk + 3][lrow] = av0.w;
        Ast[lk + 0][lrow + 32] = av1.x; Ast[lk + 1][lrow + 32] = av1.y;
        Ast[lk + 2][lrow + 32] = av1.z; Ast[lk + 3][lrow + 32] = av1.w;
        Bst[lk + 0][lrow] = bv0.x; Bst[lk + 1][lrow] = bv0.y;
        Bst[lk + 2][lrow] = bv0.z; Bst[lk + 3][lrow] = bv0.w;
        Bst[lk + 0][lrow + 32] = bv1.x; Bst[lk + 1][lrow + 32] = bv1.y;
        Bst[lk + 2][lrow + 32] = bv1.z; Bst[lk + 3][lrow + 32] = bv1.w;
        __syncthreads();
        #pragma unroll
        for (int k = 0; k < 32; k++) {
            float4 a = *(const float4*)&Ast[k][ty * 4];
            float4 b = *(const float4*)&Bst[k][tx * 4];
            acc[0][0] = fmaf(a.x, b.x, acc[0][0]);
            acc[0][1] = fmaf(a.x, b.y, acc[0][1]);
            acc[0][2] = fmaf(a.x, b.z, acc[0][2]);
            acc[0][3] = fmaf(a.x, b.w, acc[0][3]);
            acc[1][0] = fmaf(a.y, b.x, acc[1][0]);
            acc[1][1] = fmaf(a.y, b.y, acc[1][1]);
            acc[1][2] = fmaf(a.y, b.z, acc[1][2]);
            acc[1][3] = fmaf(a.y, b.w, acc[1][3]);
            acc[2][0] = fmaf(a.z, b.x, acc[2][0]);
            acc[2][1] = fmaf(a.z, b.y, acc[2][1]);
            acc[2][2] = fmaf(a.z, b.z, acc[2][2]);
            acc[2][3] = fmaf(a.z, b.w, acc[2][3]);
            acc[3][0] = fmaf(a.w, b.x, acc[3][0]);
            acc[3][1] = fmaf(a.w, b.y, acc[3][1]);
            acc[3][2] = fmaf(a.w, b.z, acc[3][2]);
            acc[3][3] = fmaf(a.w, b.w, acc[3][3]);
        }
    }

    const float b0 = bias[nBase + tx * 4 + 0];
    const float b1 = bias[nBase + tx * 4 + 1];
    const float b2 = bias[nBase + tx * 4 + 2];
    const float b3 = bias[nBase + tx * 4 + 3];
    #pragma unroll
    for (int i = 0; i < 4; i++) {
        float4 o;
        o.x = acc[i][0] + b0; o.y = acc[i][1] + b1;
        o.z = acc[i][2] + b2; o.w = acc[i][3] + b3;
        *(float4*)&C[(size_t)(mBase + ty * 4 + i) * N + nBase + tx * 4] = o;
    }
}

// ---------------------------------------------------------------------------
// Persistent recurrent kernel, round 2: h = tanh(pre_t + h @ wR), 512 steps.
// Grid = 128 CTAs (4 b-tiles of 16 x 32 j-tiles of 32), 256 threads.
//
// Thread decomposition (register blocking in b to fix the LDS bottleneck):
//   jg = tid & 15   -> j columns {jbase+jg, jbase+jg+16}   (rj = 2)
//   bq = (tid>>4)&3 -> b rows bBase + bq*4 .. +3           (rb = 4)
//   ks = tid >> 6   -> k range [ks*256, ks*256+256)        (4-way k-split)
//
// Per 4-k iteration per thread: 2 LDS.128 (wR) + 4 broadcast LDG.128 (h)
// + 32 FFMA. Per SM per iteration: FFMA 128 cyc (binding), crossbar 64 cyc,
// LDG-issue ~58 cyc. k-split partials reduced via smem, then tanh + store.
// ---------------------------------------------------------------------------
__global__ void __launch_bounds__(REC_THREADS, 1) rnn_rec_kernel(
    const float* __restrict__ pre,
    const float* __restrict__ h0,
    const float* __restrict__ wR,
    float* __restrict__ hid)
{
    extern __shared__ float smemf[];
    float* wRs = smemf;                    // [32][1028]
    float* red = smemf + WR_SMEM_FLOATS;   // [4 ksplit][512 outputs]

    const int tid   = threadIdx.x;
    const int bx    = blockIdx.x;
    const int jbase = (bx & 31) * 32;
    const int bBase = (bx >> 5) * 16;

    // Stage this CTA's wR slice: wRs[jj][k] = wR[k*H + jbase + jj]
    for (int idx = tid; idx < 32 * HH; idx += REC_THREADS) {
        int jj = idx & 31;
        int k  = idx >> 5;
        wRs[jj * 1028 + k] = wR[k * HH + jbase + jj];
    }
    // Broadcast h0 -> g_h0b[b][k]
    for (int idx = bx * REC_THREADS + tid; idx < BB * HH; idx += REC_CTAS * REC_THREADS) {
        g_h0b[idx] = h0[idx & (HH - 1)];
    }
    grid_sync();

    const int jg = tid & 15;
    const int bq = (tid >> 4) & 3;
    const int ks = tid >> 6;
    const int kBeg = ks * 256;

    const float* w0p = wRs + jg * 1028 + kBeg;
    const float* w1p = wRs + (jg + 16) * 1028 + kBeg;
    const int bRow = bBase + bq * 4;        // first of 4 b rows

    // Reduce-phase constants: this thread reduces outputs o0=tid, o1=tid+256
    const int o0 = tid, o1 = tid + 256;
    const int rb0 = bBase + (o0 >> 5), rj0 = jbase + (o0 & 31);
    const int rb1 = bBase + (o1 >> 5), rj1 = jbase + (o1 & 31);

    const float* hOld = g_h0b;
    for (int t = 0; t < TT; t++) {
        // Prefetch pre values for the reduce phase (hides DRAM latency
        // behind the k-loop).
        const float* preT = pre + (size_t)t * (BB * HH);
        float pv0 = __ldg(preT + rb0 * HH + rj0);
        float pv1 = __ldg(preT + rb1 * HH + rj1);

        const float* h0r = hOld + (bRow + 0) * HH + kBeg;
        const float* h1r = hOld + (bRow + 1) * HH + kBeg;
        const float* h2r = hOld + (bRow + 2) * HH + kBeg;
        const float* h3r = hOld + (bRow + 3) * HH + kBeg;

        float a00 = 0.f, a01 = 0.f;   // b+0 x {j0, j1}
        float a10 = 0.f, a11 = 0.f;
        float a20 = 0.f, a21 = 0.f;
        float a30 = 0.f, a31 = 0.f;

        #pragma unroll 4
        for (int k = 0; k < 256; k += 4) {
            const float4 w0 = *reinterpret_cast<const float4*>(w0p + k);
            const float4 w1 = *reinterpret_cast<const float4*>(w1p + k);
            const float4 hv0 = *reinterpret_cast<const float4*>(h0r + k);
            const float4 hv1 = *reinterpret_cast<const float4*>(h1r + k);
            const float4 hv2 = *reinterpret_cast<const float4*>(h2r + k);
            const float4 hv3 = *reinterpret_cast<const float4*>(h3r + k);

            a00 = fmaf(hv0.x, w0.x, a00); a00 = fmaf(hv0.y, w0.y, a00);
            a00 = fmaf(hv0.z, w0.z, a00); a00 = fmaf(hv0.w, w0.w, a00);
            a01 = fmaf(hv0.x, w1.x, a01); a01 = fmaf(hv0.y, w1.y, a01);
            a01 = fmaf(hv0.z, w1.z, a01); a01 = fmaf(hv0.w, w1.w, a01);

            a10 = fmaf(hv1.x, w0.x, a10); a10 = fmaf(hv1.y, w0.y, a10);
            a10 = fmaf(hv1.z, w0.z, a10); a10 = fmaf(hv1.w, w0.w, a10);
            a11 = fmaf(hv1.x, w1.x, a11); a11 = fmaf(hv1.y, w1.y, a11);
            a11 = fmaf(hv1.z, w1.z, a11); a11 = fmaf(hv1.w, w1.w, a11);

            a20 = fmaf(hv2.x, w0.x, a20); a20 = fmaf(hv2.y, w0.y, a20);
            a20 = fmaf(hv2.z, w0.z, a20); a20 = fmaf(hv2.w, w0.w, a20);
            a21 = fmaf(hv2.x, w1.x, a21); a21 = fmaf(hv2.y, w1.y, a21);
            a21 = fmaf(hv2.z, w1.z, a21); a21 = fmaf(hv2.w, w1.w, a21);

            a30 = fmaf(hv3.x, w0.x, a30); a30 = fmaf(hv3.y, w0.y, a30);
            a30 = fmaf(hv3.z, w0.z, a30); a30 = fmaf(hv3.w, w0.w, a30);
            a31 = fmaf(hv3.x, w1.x, a31); a31 = fmaf(hv3.y, w1.y, a31);
            a31 = fmaf(hv3.z, w1.z, a31); a31 = fmaf(hv3.w, w1.w, a31);
        }

        // Write 8 partials: red[ks*512 + b_local*32 + j_local]
        {
            float* rp = red + ks * 512 + (bq * 4) * 32 + jg;
            rp[0 * 32 +  0] = a00;  rp[0 * 32 + 16] = a01;
            rp[1 * 32 +  0] = a10;  rp[1 * 32 + 16] = a11;
            rp[2 * 32 +  0] = a20;  rp[2 * 32 + 16] = a21;
            rp[3 * 32 +  0] = a30;  rp[3 * 32 + 16] = a31;
        }
        __syncthreads();

        // Reduce 4 k-split partials, add pre, tanh, store to hidden output.
        float* hNew = hid + (size_t)t * (BB * HH);
        {
            float s0 = (red[o0] + red[512 + o0]) + (red[1024 + o0] + red[1536 + o0]);
            float s1 = (red[o1] + red[512 + o1]) + (red[1024 + o1] + red[1536 + o1]);
            hNew[rb0 * HH + rj0] = tanhf(pv0 + s0);
            hNew[rb1 * HH + rj1] = tanhf(pv1 + s1);
        }
        grid_sync();                 // h_t fully visible before step t+1
        hOld = hNew;
    }
}

// ---------------------------------------------------------------------------
// Launch: pre-GEMM -> persistent recurrence -> output GEMM.
// ---------------------------------------------------------------------------
extern "C" void kernel_launch(void* const* d_in, const int* in_sizes, int n_in,
                              void* d_out, int out_size)
{
    const float* x  = (const float*)d_in[0];
    const float* h0 = (const float*)d_in[1];
    const float* wI = (const float*)d_in[2];
    const float* wR = (const float*)d_in[3];
    const float* wO = (const float*)d_in[4];
    const float* bR = (const float*)d_in[5];
    const float* bO = (const float*)d_in[6];

    float* outp = (float*)d_out;            // [T,B,O]
    float* hid  = outp + OUT_ELEMS;         // [T,B,H]

    float* pre = nullptr;
    cudaGetSymbolAddress((void**)&pre, g_pre);
    cudaFuncSetAttribute(rnn_rec_kernel,
                         cudaFuncAttributeMaxDynamicSharedMemorySize,
                         REC_SMEM_BYTES);

    // pre[T*B, H] = x[T*B, I] @ wI[H, I]^T + bR
    gemm_tn_kernel<<<dim3((TT * BB) / 64, HH / 64, 1), 256>>>(
        x, wI, bR, pre, TT * BB, HH, II);

    // hidden_states (written straight into d_out's hidden section)
    rnn_rec_kernel<<<REC_CTAS, REC_THREADS, REC_SMEM_BYTES>>>(pre, h0, wR, hid);

    // outputs[T*B, O] = hid[T*B, H] @ wO[O, H]^T + bO
    gemm_tn_kernel<<<dim3((TT * BB) / 64, OO / 64, 1), 256>>>(
        hid, wO, bO, outp, TT * BB, OO, HH);
}

// round 5
// speedup vs baseline: 2.1812x; 1.2144x over previous
#include <cuda_runtime.h>
#include <cuda_bf16.h>
#include <cstdint>

// Problem constants
#define TT 512
#define BB 64
#define II 256
#define HH 1024
#define OO 256

#define OUT_ELEMS   (TT * BB * OO)        // outputs section
#define HID_ELEMS   (TT * BB * HH)        // hidden section
#define PRE_ELEMS   (TT * BB * HH)

#define REC_CTAS    128
#define REC_THREADS 256
#define WR_FLOATS   (32 * 1028)           // wR slice [32 j][1024 k] padded
#define HS_FLOATS   (16 * 1028)           // h stage  [16 b][1024 k] padded
#define RED_FLOATS  2048                  // 4 ksplit x 512 outputs
#define REC_SMEM_BYTES ((WR_FLOATS + HS_FLOATS + RED_FLOATS) * 4)  // 205568

// Scratch (device globals: no cudaMalloc allowed)
__device__ float    g_pre[PRE_ELEMS];     // x @ wI^T + bR, [T*B][H]
__device__ float    g_h0b[BB * HH];       // h0 broadcast to [B][H]
__device__ unsigned g_arrived = 0;        // monotonic ticket (startup sync only)
__device__ unsigned g_flags[4][32][32];   // [bt][jt][pad to 128B line]

// ---------------------------------------------------------------------------
// Grid-wide barrier (used ONCE at startup): monotonic ticket, wrap-safe.
// ---------------------------------------------------------------------------
__device__ __forceinline__ void grid_sync() {
    __syncthreads();
    if (threadIdx.x == 0) {
        __threadfence();
        unsigned ticket = atomicAdd(&g_arrived, 1u) + 1u;
        unsigned target = ((ticket + (REC_CTAS - 1u)) / REC_CTAS) * REC_CTAS;
        unsigned cur;
        do {
            asm volatile("ld.acquire.gpu.global.u32 %0, [%1];"
                         : "=r"(cur) : "l"(&g_arrived) : "memory");
        } while ((int)(cur - target) < 0);
        __threadfence();
    }
    __syncthreads();
}

// ---------------------------------------------------------------------------
// Generic fp32 GEMM:  C[M,N] = A[M,K] @ B[N,K]^T + bias[N]
// (unchanged — measured at the SIMT FFMA roofline)
// ---------------------------------------------------------------------------
__global__ void __launch_bounds__(256) gemm_tn_kernel(
    const float* __restrict__ A, const float* __restrict__ B,
    const float* __restrict__ bias, float* __restrict__ C,
    int M, int N, int K)
{
    __shared__ float Ast[32][68];
    __shared__ float Bst[32][68];

    const int tid   = threadIdx.x;
    const int mBase = blockIdx.x * 64;
    const int nBase = blockIdx.y * 64;
    const int lrow  = tid >> 3;
    const int lk    = (tid & 7) << 2;
    const int tx    = tid & 15;
    const int ty    = tid >> 4;

    float acc[4][4] = {};

    const float* Ap = A + (size_t)(mBase + lrow) * K + lk;
    const float* Bp = B + (size_t)(nBase + lrow) * K + lk;

    for (int k0 = 0; k0 < K; k0 += 32) {
        float4 av0 = *(const float4*)(Ap + k0);
        float4 av1 = *(const float4*)(Ap + (size_t)32 * K + k0);
        float4 bv0 = *(const float4*)(Bp + k0);
        float4 bv1 = *(const float4*)(Bp + (size_t)32 * K + k0);
        __syncthreads();
        Ast[lk + 0][lrow] = av0.x; Ast[lk + 1][lrow] = av0.y;
        Ast[lk + 2][lrow] = av0.z; Ast[lk + 3][lrow] = av0.w;
        Ast[lk + 0][lrow + 32] = av1.x; Ast[lk + 1][lrow + 32] = av1.y;
        Ast[lk + 2][lrow + 32] = av1.z; Ast[lk + 3][lrow + 32] = av1.w;
        Bst[lk + 0][lrow] = bv0.x; Bst[lk + 1][lrow] = bv0.y;
        Bst[lk + 2][lrow] = bv0.z; Bst[lk + 3][lrow] = bv0.w;
        Bst[lk + 0][lrow + 32] = bv1.x; Bst[lk + 1][lrow + 32] = bv1.y;
        Bst[lk + 2][lrow + 32] = bv1.z; Bst[lk + 3][lrow + 32] = bv1.w;
        __syncthreads();
        #pragma unroll
        for (int k = 0; k < 32; k++) {
            float4 a = *(const float4*)&Ast[k][ty * 4];
            float4 b = *(const float4*)&Bst[k][tx * 4];
            acc[0][0] = fmaf(a.x, b.x, acc[0][0]);
            acc[0][1] = fmaf(a.x, b.y, acc[0][1]);
            acc[0][2] = fmaf(a.x, b.z, acc[0][2]);
            acc[0][3] = fmaf(a.x, b.w, acc[0][3]);
            acc[1][0] = fmaf(a.y, b.x, acc[1][0]);
            acc[1][1] = fmaf(a.y, b.y, acc[1][1]);
            acc[1][2] = fmaf(a.y, b.z, acc[1][2]);
            acc[1][3] = fmaf(a.y, b.w, acc[1][3]);
            acc[2][0] = fmaf(a.z, b.x, acc[2][0]);
            acc[2][1] = fmaf(a.z, b.y, acc[2][1]);
            acc[2][2] = fmaf(a.z, b.z, acc[2][2]);
            acc[2][3] = fmaf(a.z, b.w, acc[2][3]);
            acc[3][0] = fmaf(a.w, b.x, acc[3][0]);
            acc[3][1] = fmaf(a.w, b.y, acc[3][1]);
            acc[3][2] = fmaf(a.w, b.z, acc[3][2]);
            acc[3][3] = fmaf(a.w, b.w, acc[3][3]);
        }
    }

    const float b0 = bias[nBase + tx * 4 + 0];
    const float b1 = bias[nBase + tx * 4 + 1];
    const float b2 = bias[nBase + tx * 4 + 2];
    const float b3 = bias[nBase + tx * 4 + 3];
    #pragma unroll
    for (int i = 0; i < 4; i++) {
        float4 o;
        o.x = acc[i][0] + b0; o.y = acc[i][1] + b1;
        o.z = acc[i][2] + b2; o.w = acc[i][3] + b3;
        *(float4*)&C[(size_t)(mBase + ty * 4 + i) * N + nBase + tx * 4] = o;
    }
}

// ---------------------------------------------------------------------------
// Persistent recurrent kernel, round 3: h = tanh(pre_t + h @ wR), 512 steps.
// Grid = 128 CTAs (4 b-tiles x 32 j-tiles), 256 threads.
//
// Changes vs round 2:
//  * Group-local flag sync: CTA (bt, jt) only depends on the 32 CTAs with the
//    same bt. Writer: threadfence + one st.release.gpu; reader: 32 lanes poll
//    32 per-CTA flags (one 128B line each). No atomic serialization, 4
//    independent groups.
//  * h[16 x 1024] staged into smem each step (pad stride 1028) -> k-loop is
//    pure LDS+FFMA, no mid-loop global latency.
// ---------------------------------------------------------------------------
__global__ void __launch_bounds__(REC_THREADS, 1) rnn_rec_kernel(
    const float* __restrict__ pre,
    const float* __restrict__ h0,
    const float* __restrict__ wR,
    float* __restrict__ hid)
{
    extern __shared__ float smemf[];
    float* wRs = smemf;                          // [32][1028]
    float* hs  = smemf + WR_FLOATS;              // [16][1028]
    float* red = smemf + WR_FLOATS + HS_FLOATS;  // [4][512]

    const int tid   = threadIdx.x;
    const int bx    = blockIdx.x;
    const int jt    = bx & 31;
    const int bt    = bx >> 5;
    const int jbase = jt * 32;
    const int bBase = bt * 16;

    // Stage this CTA's wR slice: wRs[jj][k] = wR[k*H + jbase + jj]
    for (int idx = tid; idx < 32 * HH; idx += REC_THREADS) {
        int jj = idx & 31;
        int k  = idx >> 5;
        wRs[jj * 1028 + k] = wR[k * HH + jbase + jj];
    }
    // Broadcast h0 -> g_h0b[b][k]
    for (int idx = bx * REC_THREADS + tid; idx < BB * HH; idx += REC_CTAS * REC_THREADS) {
        g_h0b[idx] = h0[idx & (HH - 1)];
    }
    // Reset this CTA's step flag (graph replays reuse module state).
    if (tid == 0) g_flags[bt][jt][0] = 0u;
    grid_sync();   // resets + h0 broadcast + wR staging all visible

    const int jg = tid & 15;
    const int bq = (tid >> 4) & 3;
    const int ks = tid >> 6;
    const int kBeg = ks * 256;

    const float* w0p = wRs + jg * 1028 + kBeg;
    const float* w1p = wRs + (jg + 16) * 1028 + kBeg;
    const float* hsp = hs + (bq * 4) * 1028 + kBeg;

    // Reduce-phase constants: this thread reduces outputs o0=tid, o1=tid+256
    const int o0 = tid, o1 = tid + 256;
    const int rb0 = bBase + (o0 >> 5), rj0 = jbase + (o0 & 31);
    const int rb1 = bBase + (o1 >> 5), rj1 = jbase + (o1 & 31);

    unsigned* myFlag = &g_flags[bt][jt][0];

    const float* hOldG = g_h0b + bBase * HH;     // global source of h_(t-1)
    for (int t = 0; t < TT; t++) {
        // Prefetch pre values (independent of the flag wait; hides DRAM).
        const float* preT = pre + (size_t)t * (BB * HH);
        float pv0 = __ldg(preT + rb0 * HH + rj0);
        float pv1 = __ldg(preT + rb1 * HH + rj1);

        // Wait for all 32 producers of this b-tile to have published h_(t-1).
        if (t > 0 && tid < 32) {
            const unsigned* f = &g_flags[bt][tid][0];
            unsigned cur;
            do {
                asm volatile("ld.acquire.gpu.global.u32 %0, [%1];"
                             : "=r"(cur) : "l"(f) : "memory");
            } while (cur < (unsigned)t);
        }
        __syncthreads();

        // Stage h_(t-1)[16 rows x 1024] into smem (coalesced, pad 1028).
        {
            const float4* src = reinterpret_cast<const float4*>(hOldG);
            #pragma unroll
            for (int i = 0; i < 16; i++) {
                int idx  = tid + i * REC_THREADS;      // 0..4095
                int row  = idx >> 8;
                int c4   = idx & 255;
                float4 v = src[row * (HH / 4) + c4];
                *reinterpret_cast<float4*>(hs + row * 1028 + c4 * 4) = v;
            }
        }
        __syncthreads();

        float a00 = 0.f, a01 = 0.f;   // b+0 x {j0, j1}
        float a10 = 0.f, a11 = 0.f;
        float a20 = 0.f, a21 = 0.f;
        float a30 = 0.f, a31 = 0.f;

        #pragma unroll 4
        for (int k = 0; k < 256; k += 4) {
            const float4 w0 = *reinterpret_cast<const float4*>(w0p + k);
            const float4 w1 = *reinterpret_cast<const float4*>(w1p + k);
            const float4 hv0 = *reinterpret_cast<const float4*>(hsp + 0 * 1028 + k);
            const float4 hv1 = *reinterpret_cast<const float4*>(hsp + 1 * 1028 + k);
            const float4 hv2 = *reinterpret_cast<const float4*>(hsp + 2 * 1028 + k);
            const float4 hv3 = *reinterpret_cast<const float4*>(hsp + 3 * 1028 + k);

            a00 = fmaf(hv0.x, w0.x, a00); a00 = fmaf(hv0.y, w0.y, a00);
            a00 = fmaf(hv0.z, w0.z, a00); a00 = fmaf(hv0.w, w0.w, a00);
            a01 = fmaf(hv0.x, w1.x, a01); a01 = fmaf(hv0.y, w1.y, a01);
            a01 = fmaf(hv0.z, w1.z, a01); a01 = fmaf(hv0.w, w1.w, a01);

            a10 = fmaf(hv1.x, w0.x, a10); a10 = fmaf(hv1.y, w0.y, a10);
            a10 = fmaf(hv1.z, w0.z, a10); a10 = fmaf(hv1.w, w0.w, a10);
            a11 = fmaf(hv1.x, w1.x, a11); a11 = fmaf(hv1.y, w1.y, a11);
            a11 = fmaf(hv1.z, w1.z, a11); a11 = fmaf(hv1.w, w1.w, a11);

            a20 = fmaf(hv2.x, w0.x, a20); a20 = fmaf(hv2.y, w0.y, a20);
            a20 = fmaf(hv2.z, w0.z, a20); a20 = fmaf(hv2.w, w0.w, a20);
            a21 = fmaf(hv2.x, w1.x, a21); a21 = fmaf(hv2.y, w1.y, a21);
            a21 = fmaf(hv2.z, w1.z, a21); a21 = fmaf(hv2.w, w1.w, a21);

            a30 = fmaf(hv3.x, w0.x, a30); a30 = fmaf(hv3.y, w0.y, a30);
            a30 = fmaf(hv3.z, w0.z, a30); a30 = fmaf(hv3.w, w0.w, a30);
            a31 = fmaf(hv3.x, w1.x, a31); a31 = fmaf(hv3.y, w1.y, a31);
            a31 = fmaf(hv3.z, w1.z, a31); a31 = fmaf(hv3.w, w1.w, a31);
        }

        // Write 8 partials: red[ks*512 + b_local*32 + j_local]
        {
            float* rp = red + ks * 512 + (bq * 4) * 32 + jg;
            rp[0 * 32 +  0] = a00;  rp[0 * 32 + 16] = a01;
            rp[1 * 32 +  0] = a10;  rp[1 * 32 + 16] = a11;
            rp[2 * 32 +  0] = a20;  rp[2 * 32 + 16] = a21;
            rp[3 * 32 +  0] = a30;  rp[3 * 32 + 16] = a31;
        }
        __syncthreads();

        // Reduce k-split partials, add pre, tanh, store h_t.
        float* hNew = hid + (size_t)t * (BB * HH);
        {
            float s0 = (red[o0] + red[512 + o0]) + (red[1024 + o0] + red[1536 + o0]);
            float s1 = (red[o1] + red[512 + o1]) + (red[1024 + o1] + red[1536 + o1]);
            hNew[rb0 * HH + rj0] = tanhf(pv0 + s0);
            hNew[rb1 * HH + rj1] = tanhf(pv1 + s1);
        }

        // Publish h_t to the group: fence all threads' stores, then release.
        __threadfence();
        __syncthreads();
        if (tid == 0) {
            unsigned v = (unsigned)(t + 1);
            asm volatile("st.release.gpu.global.u32 [%0], %1;"
                         :: "l"(myFlag), "r"(v) : "memory");
        }

        hOldG = hNew + bBase * HH;
    }
}

// ---------------------------------------------------------------------------
// Launch: pre-GEMM -> persistent recurrence -> output GEMM.
// ---------------------------------------------------------------------------
extern "C" void kernel_launch(void* const* d_in, const int* in_sizes, int n_in,
                              void* d_out, int out_size)
{
    const float* x  = (const float*)d_in[0];
    const float* h0 = (const float*)d_in[1];
    const float* wI = (const float*)d_in[2];
    const float* wR = (const float*)d_in[3];
    const float* wO = (const float*)d_in[4];
    const float* bR = (const float*)d_in[5];
    const float* bO = (const float*)d_in[6];

    float* outp = (float*)d_out;            // [T,B,O]
    float* hid  = outp + OUT_ELEMS;         // [T,B,H]

    float* pre = nullptr;
    cudaGetSymbolAddress((void**)&pre, g_pre);
    cudaFuncSetAttribute(rnn_rec_kernel,
                         cudaFuncAttributeMaxDynamicSharedMemorySize,
                         REC_SMEM_BYTES);

    // pre[T*B, H] = x[T*B, I] @ wI[H, I]^T + bR
    gemm_tn_kernel<<<dim3((TT * BB) / 64, HH / 64, 1), 256>>>(
        x, wI, bR, pre, TT * BB, HH, II);

    // hidden_states (written straight into d_out's hidden section)
    rnn_rec_kernel<<<REC_CTAS, REC_THREADS, REC_SMEM_BYTES>>>(pre, h0, wR, hid);

    // outputs[T*B, O] = hid[T*B, H] @ wO[O, H]^T + bO
    gemm_tn_kernel<<<dim3((TT * BB) / 64, OO / 64, 1), 256>>>(
        hid, wO, bO, outp, TT * BB, OO, HH);
}

// round 7
// speedup vs baseline: 2.3813x; 1.0917x over previous
#include <cuda_runtime.h>
#include <cuda_bf16.h>
#include <cstdint>

// Problem constants
#define TT 512
#define BB 64
#define II 256
#define HH 1024
#define OO 256

#define OUT_ELEMS   (TT * BB * OO)
#define HID_ELEMS   (TT * BB * HH)
#define PRE_ELEMS   (TT * BB * HH)

#define REC_CTAS    128
#define REC_THREADS 256
#define WR_FLOATS   (32 * 1028)           // wR slice [32 j][1024 k] padded
#define HS_FLOATS   (16 * 1028)           // h stage  [16 b][1024 k] padded
#define RED_FLOATS  (8 * 512)             // 8 ksplit x 512 outputs
#define REC_SMEM_BYTES ((WR_FLOATS + HS_FLOATS + RED_FLOATS) * 4)  // 213760

// Scratch (device globals: no cudaMalloc allowed)
__device__ float    g_pre[PRE_ELEMS];
__device__ float    g_h0b[BB * HH];
__device__ unsigned g_arrived = 0;        // monotonic ticket (startup only)
__device__ unsigned g_flags[4][32][32];   // [bt][jt][pad to 128B line]

__device__ __forceinline__ void grid_sync() {
    __syncthreads();
    if (threadIdx.x == 0) {
        __threadfence();
        unsigned ticket = atomicAdd(&g_arrived, 1u) + 1u;
        unsigned target = ((ticket + (REC_CTAS - 1u)) / REC_CTAS) * REC_CTAS;
        unsigned cur;
        do {
            asm volatile("ld.acquire.gpu.global.u32 %0, [%1];"
                         : "=r"(cur) : "l"(&g_arrived) : "memory");
        } while ((int)(cur - target) < 0);
        __threadfence();
    }
    __syncthreads();
}

// ---------------------------------------------------------------------------
// Generic fp32 GEMM:  C[M,N] = A[M,K] @ B[N,K]^T + bias[N]   (unchanged)
// ---------------------------------------------------------------------------
__global__ void __launch_bounds__(256) gemm_tn_kernel(
    const float* __restrict__ A, const float* __restrict__ B,
    const float* __restrict__ bias, float* __restrict__ C,
    int M, int N, int K)
{
    __shared__ float Ast[32][68];
    __shared__ float Bst[32][68];

    const int tid   = threadIdx.x;
    const int mBase = blockIdx.x * 64;
    const int nBase = blockIdx.y * 64;
    const int lrow  = tid >> 3;
    const int lk    = (tid & 7) << 2;
    const int tx    = tid & 15;
    const int ty    = tid >> 4;

    float acc[4][4] = {};

    const float* Ap = A + (size_t)(mBase + lrow) * K + lk;
    const float* Bp = B + (size_t)(nBase + lrow) * K + lk;

    for (int k0 = 0; k0 < K; k0 += 32) {
        float4 av0 = *(const float4*)(Ap + k0);
        float4 av1 = *(const float4*)(Ap + (size_t)32 * K + k0);
        float4 bv0 = *(const float4*)(Bp + k0);
        float4 bv1 = *(const float4*)(Bp + (size_t)32 * K + k0);
        __syncthreads();
        Ast[lk + 0][lrow] = av0.x; Ast[lk + 1][lrow] = av0.y;
        Ast[lk + 2][lrow] = av0.z; Ast[lk + 3][lrow] = av0.w;
        Ast[lk + 0][lrow + 32] = av1.x; Ast[lk + 1][lrow + 32] = av1.y;
        Ast[lk + 2][lrow + 32] = av1.z; Ast[lk + 3][lrow + 32] = av1.w;
        Bst[lk + 0][lrow] = bv0.x; Bst[lk + 1][lrow] = bv0.y;
        Bst[lk + 2][lrow] = bv0.z; Bst[lk + 3][lrow] = bv0.w;
        Bst[lk + 0][lrow + 32] = bv1.x; Bst[lk + 1][lrow + 32] = bv1.y;
        Bst[lk + 2][lrow + 32] = bv1.z; Bst[lk + 3][lrow + 32] = bv1.w;
        __syncthreads();
        #pragma unroll
        for (int k = 0; k < 32; k++) {
            float4 a = *(const float4*)&Ast[k][ty * 4];
            float4 b = *(const float4*)&Bst[k][tx * 4];
            acc[0][0] = fmaf(a.x, b.x, acc[0][0]);
            acc[0][1] = fmaf(a.x, b.y, acc[0][1]);
            acc[0][2] = fmaf(a.x, b.z, acc[0][2]);
            acc[0][3] = fmaf(a.x, b.w, acc[0][3]);
            acc[1][0] = fmaf(a.y, b.x, acc[1][0]);
            acc[1][1] = fmaf(a.y, b.y, acc[1][1]);
            acc[1][2] = fmaf(a.y, b.z, acc[1][2]);
            acc[1][3] = fmaf(a.y, b.w, acc[1][3]);
            acc[2][0] = fmaf(a.z, b.x, acc[2][0]);
            acc[2][1] = fmaf(a.z, b.y, acc[2][1]);
            acc[2][2] = fmaf(a.z, b.z, acc[2][2]);
            acc[2][3] = fmaf(a.z, b.w, acc[2][3]);
            acc[3][0] = fmaf(a.w, b.x, acc[3][0]);
            acc[3][1] = fmaf(a.w, b.y, acc[3][1]);
            acc[3][2] = fmaf(a.w, b.z, acc[3][2]);
            acc[3][3] = fmaf(a.w, b.w, acc[3][3]);
        }
    }

    const float b0 = bias[nBase + tx * 4 + 0];
    const float b1 = bias[nBase + tx * 4 + 1];
    const float b2 = bias[nBase + tx * 4 + 2];
    const float b3 = bias[nBase + tx * 4 + 3];
    #pragma unroll
    for (int i = 0; i < 4; i++) {
        float4 o;
        o.x = acc[i][0] + b0; o.y = acc[i][1] + b1;
        o.z = acc[i][2] + b2; o.w = acc[i][3] + b3;
        *(float4*)&C[(size_t)(mBase + ty * 4 + i) * N + nBase + tx * 4] = o;
    }
}

// ---------------------------------------------------------------------------
// Persistent recurrent kernel, round 5: h = tanh(pre_t + h @ wR), 512 steps.
// Grid = 128 CTAs (4 b-tiles x 32 j-tiles), 256 threads.
//
// Thread mapping (broadcast-friendly, bank-conflict-free):
//   jg = tid & 7          -> 4 j columns:  j = jg + 8*i      (i = 0..3)
//   bq = (tid >> 3) & 3   -> 4 b rows:     b = bq + 4*r      (r = 0..3)
//   ks = tid >> 5         -> k range [ks*128, ks*128+128)    (8-way k-split)
//
// Per warp per 4-k: w-LDS has 8 distinct 16B addrs (bq broadcast) on distinct
// bank groups -> 1 cyc; h-LDS has 4 distinct (jg broadcast) -> 1 cyc.
// Crossbar ~25% of FFMA time; FFMA is binding at 8192 cyc/step/SM.
// ---------------------------------------------------------------------------
__global__ void __launch_bounds__(REC_THREADS, 1) rnn_rec_kernel(
    const float* __restrict__ pre,
    const float* __restrict__ h0,
    const float* __restrict__ wR,
    float* __restrict__ hid)
{
    extern __shared__ float smemf[];
    float* wRs = smemf;                          // [32 j][1028]
    float* hs  = smemf + WR_FLOATS;              // [16 b][1028]
    float* red = smemf + WR_FLOATS + HS_FLOATS;  // [8 ks][512] (j-permuted)

    const int tid   = threadIdx.x;
    const int bx    = blockIdx.x;
    const int jt    = bx & 31;
    const int bt    = bx >> 5;
    const int jbase = jt * 32;
    const int bBase = bt * 16;

    // Stage this CTA's wR slice: wRs[jj][k] = wR[k*H + jbase + jj]
    for (int idx = tid; idx < 32 * HH; idx += REC_THREADS) {
        int jj = idx & 31;
        int k  = idx >> 5;
        wRs[jj * 1028 + k] = wR[k * HH + jbase + jj];
    }
    // Broadcast h0 -> g_h0b[b][k]
    for (int idx = bx * REC_THREADS + tid; idx < BB * HH; idx += REC_CTAS * REC_THREADS) {
        g_h0b[idx] = h0[idx & (HH - 1)];
    }
    if (tid == 0) g_flags[bt][jt][0] = 0u;   // reset for this graph replay
    grid_sync();

    const int jg = tid & 7;
    const int bq = (tid >> 3) & 3;
    const int ks = tid >> 5;
    const int kBeg = ks * 128;

    const float* wp0 = wRs + (jg +  0) * 1028 + kBeg;
    const float* wp1 = wRs + (jg +  8) * 1028 + kBeg;
    const float* wp2 = wRs + (jg + 16) * 1028 + kBeg;
    const float* wp3 = wRs + (jg + 24) * 1028 + kBeg;
    const float* hp0 = hs + (bq +  0) * 1028 + kBeg;
    const float* hp1 = hs + (bq +  4) * 1028 + kBeg;
    const float* hp2 = hs + (bq +  8) * 1028 + kBeg;
    const float* hp3 = hs + (bq + 12) * 1028 + kBeg;

    // Reduce-phase constants: thread reduces outputs o0=tid, o1=tid+256.
    // red index o: b_local = o>>5, j' = o&31, actual j = (j'>>2) + ((j'&3)<<3)
    const int o0 = tid, o1 = tid + 256;
    const int rb0 = bBase + (o0 >> 5);
    const int rb1 = bBase + (o1 >> 5);
    const int rj0 = jbase + ((o0 & 31) >> 2) + ((o0 & 3) << 3);
    const int rj1 = jbase + ((o1 & 31) >> 2) + ((o1 & 3) << 3);

    unsigned* myFlag = &g_flags[bt][jt][0];

    const float* hOldG = g_h0b + bBase * HH;
    for (int t = 0; t < TT; t++) {
        // Prefetch pre values (independent of flag wait).
        const float* preT = pre + (size_t)t * (BB * HH);
        float pv0 = __ldg(preT + rb0 * HH + rj0);
        float pv1 = __ldg(preT + rb1 * HH + rj1);

        // Wait for the 32 producers of this b-tile to publish h_(t-1).
        if (t > 0 && tid < 32) {
            const unsigned* f = &g_flags[bt][tid][0];
            unsigned cur;
            do {
                asm volatile("ld.acquire.gpu.global.u32 %0, [%1];"
                             : "=r"(cur) : "l"(f) : "memory");
            } while (cur < (unsigned)t);
        }
        __syncthreads();

        // Stage h_(t-1)[16 x 1024] into smem via cp.async (pad 1028).
        {
            #pragma unroll
            for (int i = 0; i < 16; i++) {
                int idx = tid + i * REC_THREADS;   // 0..4095
                int row = idx >> 8;
                int c4  = idx & 255;
                const float* src = hOldG + row * HH + c4 * 4;
                uint32_t dst = (uint32_t)__cvta_generic_to_shared(
                                   hs + row * 1028 + c4 * 4);
                asm volatile("cp.async.cg.shared.global [%0], [%1], 16;"
                             :: "r"(dst), "l"(src));
            }
            asm volatile("cp.async.commit_group;");
            asm volatile("cp.async.wait_group 0;");
        }
        __syncthreads();

        float acc[4][4] = {};   // [r: b rows][i: j cols]

        #pragma unroll 4
        for (int k = 0; k < 128; k += 4) {
            const float4 w0 = *reinterpret_cast<const float4*>(wp0 + k);
            const float4 w1 = *reinterpret_cast<const float4*>(wp1 + k);
            const float4 w2 = *reinterpret_cast<const float4*>(wp2 + k);
            const float4 w3 = *reinterpret_cast<const float4*>(wp3 + k);
            const float4 h0v = *reinterpret_cast<const float4*>(hp0 + k);
            const float4 h1v = *reinterpret_cast<const float4*>(hp1 + k);
            const float4 h2v = *reinterpret_cast<const float4*>(hp2 + k);
            const float4 h3v = *reinterpret_cast<const float4*>(hp3 + k);

            acc[0][0] = fmaf(h0v.x, w0.x, acc[0][0]); acc[0][0] = fmaf(h0v.y, w0.y, acc[0][0]);
            acc[0][0] = fmaf(h0v.z, w0.z, acc[0][0]); acc[0][0] = fmaf(h0v.w, w0.w, acc[0][0]);
            acc[0][1] = fmaf(h0v.x, w1.x, acc[0][1]); acc[0][1] = fmaf(h0v.y, w1.y, acc[0][1]);
            acc[0][1] = fmaf(h0v.z, w1.z, acc[0][1]); acc[0][1] = fmaf(h0v.w, w1.w, acc[0][1]);
            acc[0][2] = fmaf(h0v.x, w2.x, acc[0][2]); acc[0][2] = fmaf(h0v.y, w2.y, acc[0][2]);
            acc[0][2] = fmaf(h0v.z, w2.z, acc[0][2]); acc[0][2] = fmaf(h0v.w, w2.w, acc[0][2]);
            acc[0][3] = fmaf(h0v.x, w3.x, acc[0][3]); acc[0][3] = fmaf(h0v.y, w3.y, acc[0][3]);
            acc[0][3] = fmaf(h0v.z, w3.z, acc[0][3]); acc[0][3] = fmaf(h0v.w, w3.w, acc[0][3]);

            acc[1][0] = fmaf(h1v.x, w0.x, acc[1][0]); acc[1][0] = fmaf(h1v.y, w0.y, acc[1][0]);
            acc[1][0] = fmaf(h1v.z, w0.z, acc[1][0]); acc[1][0] = fmaf(h1v.w, w0.w, acc[1][0]);
            acc[1][1] = fmaf(h1v.x, w1.x, acc[1][1]); acc[1][1] = fmaf(h1v.y, w1.y, acc[1][1]);
            acc[1][1] = fmaf(h1v.z, w1.z, acc[1][1]); acc[1][1] = fmaf(h1v.w, w1.w, acc[1][1]);
            acc[1][2] = fmaf(h1v.x, w2.x, acc[1][2]); acc[1][2] = fmaf(h1v.y, w2.y, acc[1][2]);
            acc[1][2] = fmaf(h1v.z, w2.z, acc[1][2]); acc[1][2] = fmaf(h1v.w, w2.w, acc[1][2]);
            acc[1][3] = fmaf(h1v.x, w3.x, acc[1][3]); acc[1][3] = fmaf(h1v.y, w3.y, acc[1][3]);
            acc[1][3] = fmaf(h1v.z, w3.z, acc[1][3]); acc[1][3] = fmaf(h1v.w, w3.w, acc[1][3]);

            acc[2][0] = fmaf(h2v.x, w0.x, acc[2][0]); acc[2][0] = fmaf(h2v.y, w0.y, acc[2][0]);
            acc[2][0] = fmaf(h2v.z, w0.z, acc[2][0]); acc[2][0] = fmaf(h2v.w, w0.w, acc[2][0]);
            acc[2][1] = fmaf(h2v.x, w1.x, acc[2][1]); acc[2][1] = fmaf(h2v.y, w1.y, acc[2][1]);
            acc[2][1] = fmaf(h2v.z, w1.z, acc[2][1]); acc[2][1] = fmaf(h2v.w, w1.w, acc[2][1]);
            acc[2][2] = fmaf(h2v.x, w2.x, acc[2][2]); acc[2][2] = fmaf(h2v.y, w2.y, acc[2][2]);
            acc[2][2] = fmaf(h2v.z, w2.z, acc[2][2]); acc[2][2] = fmaf(h2v.w, w2.w, acc[2][2]);
            acc[2][3] = fmaf(h2v.x, w3.x, acc[2][3]); acc[2][3] = fmaf(h2v.y, w3.y, acc[2][3]);
            acc[2][3] = fmaf(h2v.z, w3.z, acc[2][3]); acc[2][3] = fmaf(h2v.w, w3.w, acc[2][3]);

            acc[3][0] = fmaf(h3v.x, w0.x, acc[3][0]); acc[3][0] = fmaf(h3v.y, w0.y, acc[3][0]);
            acc[3][0] = fmaf(h3v.z, w0.z, acc[3][0]); acc[3][0] = fmaf(h3v.w, w0.w, acc[3][0]);
            acc[3][1] = fmaf(h3v.x, w1.x, acc[3][1]); acc[3][1] = fmaf(h3v.y, w1.y, acc[3][1]);
            acc[3][1] = fmaf(h3v.z, w1.z, acc[3][1]); acc[3][1] = fmaf(h3v.w, w1.w, acc[3][1]);
            acc[3][2] = fmaf(h3v.x, w2.x, acc[3][2]); acc[3][2] = fmaf(h3v.y, w2.y, acc[3][2]);
            acc[3][2] = fmaf(h3v.z, w2.z, acc[3][2]); acc[3][2] = fmaf(h3v.w, w2.w, acc[3][2]);
            acc[3][3] = fmaf(h3v.x, w3.x, acc[3][3]); acc[3][3] = fmaf(h3v.y, w3.y, acc[3][3]);
            acc[3][3] = fmaf(h3v.z, w3.z, acc[3][3]); acc[3][3] = fmaf(h3v.w, w3.w, acc[3][3]);
        }

        // Store partials (vector STS into j-permuted red: red[ks][b_local][j'=jg*4+i])
        {
            float* rp = red + ks * 512 + bq * 32 + jg * 4;
            *reinterpret_cast<float4*>(rp + 0 * 4 * 32) =
                make_float4(acc[0][0], acc[0][1], acc[0][2], acc[0][3]);
            *reinterpret_cast<float4*>(rp + 1 * 4 * 32) =
                make_float4(acc[1][0], acc[1][1], acc[1][2], acc[1][3]);
            *reinterpret_cast<float4*>(rp + 2 * 4 * 32) =
                make_float4(acc[2][0], acc[2][1], acc[2][2], acc[2][3]);
            *reinterpret_cast<float4*>(rp + 3 * 4 * 32) =
                make_float4(acc[3][0], acc[3][1], acc[3][2], acc[3][3]);
        }
        __syncthreads();

        // Reduce 8 k-split partials, add pre, tanh, store h_t.
        float* hNew = hid + (size_t)t * (BB * HH);
        {
            float s0 = 0.f, s1 = 0.f;
            #pragma unroll
            for (int s = 0; s < 8; s++) {
                s0 += red[s * 512 + o0];
                s1 += red[s * 512 + o1];
            }
            hNew[rb0 * HH + rj0] = tanhf(pv0 + s0);
            hNew[rb1 * HH + rj1] = tanhf(pv1 + s1);
        }

        // Publish h_t: fence all stores, then one release store.
        __threadfence();
        __syncthreads();
        if (tid == 0) {
            unsigned v = (unsigned)(t + 1);
            asm volatile("st.release.gpu.global.u32 [%0], %1;"
                         :: "l"(myFlag), "r"(v) : "memory");
        }

        hOldG = hNew + bBase * HH;
    }
}

// ---------------------------------------------------------------------------
// Launch: pre-GEMM -> persistent recurrence -> output GEMM.
// ---------------------------------------------------------------------------
extern "C" void kernel_launch(void* const* d_in, const int* in_sizes, int n_in,
                              void* d_out, int out_size)
{
    const float* x  = (const float*)d_in[0];
    const float* h0 = (const float*)d_in[1];
    const float* wI = (const float*)d_in[2];
    const float* wR = (const float*)d_in[3];
    const float* wO = (const float*)d_in[4];
    const float* bR = (const float*)d_in[5];
    const float* bO = (const float*)d_in[6];

    float* outp = (float*)d_out;            // [T,B,O]
    float* hid  = outp + OUT_ELEMS;         // [T,B,H]

    float* pre = nullptr;
    cudaGetSymbolAddress((void**)&pre, g_pre);
    cudaFuncSetAttribute(rnn_rec_kernel,
                         cudaFuncAttributeMaxDynamicSharedMemorySize,
                         REC_SMEM_BYTES);

    gemm_tn_kernel<<<dim3((TT * BB) / 64, HH / 64, 1), 256>>>(
        x, wI, bR, pre, TT * BB, HH, II);

    rnn_rec_kernel<<<REC_CTAS, REC_THREADS, REC_SMEM_BYTES>>>(pre, h0, wR, hid);

    gemm_tn_kernel<<<dim3((TT * BB) / 64, OO / 64, 1), 256>>>(
        hid, wO, bO, outp, TT * BB, OO, HH);
}